// round 5
// baseline (speedup 1.0000x reference)
#include <cuda_runtime.h>
#include <cstdint>

// Problem constants (fixed by the reference: T=8, x shape [T*32, 128, 32, 32])
#define T_STEPS   8
#define BATCH     32
#define CHANNELS  128
#define HW        1024                      // 32*32
#define N_ELEM    (BATCH*CHANNELS*HW)       // 4,194,304 spatial positions
#define GRID1     1024                      // single wave; all blocks co-resident
#define SLABS_PER_BLOCK 4                   // slabs b, b+1024, b+2048, b+3072 share channel b%128

// Scratch (static device globals — no runtime allocation permitted).
// Barrier counters are MONOTONIC across graph replays (each replay consumes
// exactly GRID1 arrivals / 1 release) -> no reset, fully deterministic.
__device__ float    g_partials[GRID1];      // per-block new_thre sum (channel = bid%128)
__device__ float    g_scale;
__device__ unsigned g_arrive  = 0;
__device__ unsigned g_release = 0;

// Block-wide deterministic sum (256 threads): shuffle tree + one smem hop.
__device__ __forceinline__ float block_sum_256(float v, float* ws) {
#pragma unroll
    for (int off = 16; off > 0; off >>= 1)
        v += __shfl_down_sync(0xFFFFFFFFu, v, off);
    const int wid = threadIdx.x >> 5;
    if ((threadIdx.x & 31) == 0) ws[wid] = v;
    __syncthreads();
    if (wid == 0) {
        v = (threadIdx.x < 8) ? ws[threadIdx.x] : 0.0f;
#pragma unroll
        for (int off = 4; off > 0; off >>= 1)
            v += __shfl_down_sync(0xFFFFFFFFu, v, off);
    }
    __syncthreads();
    return v;                 // valid in thread 0
}

// ---------------------------------------------------------------------------
// Fused persistent kernel, barrier gating only the SPARSE rewrite:
//   Phase A: read x, recurrence -> bits (smem); store ZEROS to the whole
//            output (independent of scale -> overlaps with the reads).
//   Barrier: last arriver computes the global scalar scale.
//   Phase C: rewrite only float4 groups containing spikes (scale value).
// Same thread overwrites its own addresses -> program-order safe.
// ---------------------------------------------------------------------------
__global__ __launch_bounds__(256, 7) void if_fused(const float* __restrict__ x,
                                                   const float* __restrict__ thresh,
                                                   float* __restrict__ out) {
    __shared__ uint32_t s_bits[SLABS_PER_BLOCK][256];   // packed spike bytes, 4 KiB
    __shared__ float    s_ws[8];
    __shared__ float    s_scale;
    __shared__ unsigned s_gen;
    __shared__ int      s_last;

    const float thre = __ldg(thresh);
    float local = 0.0f;
    const float4 zero4 = make_float4(0.0f, 0.0f, 0.0f, 0.0f);

    // ---- Phase A ----
#pragma unroll 1
    for (int k = 0; k < SLABS_PER_BLOCK; k++) {
        const int slab = blockIdx.x + k * GRID1;
        const int n    = slab * HW + threadIdx.x * 4;

        // 8 independent timestep loads (MLP=8).
        float4 xv[T_STEPS];
#pragma unroll
        for (int t = 0; t < T_STEPS; t++)
            xv[t] = __ldcs(reinterpret_cast<const float4*>(x + (size_t)t * N_ELEM + n));

        // Zero-fill the output for this slab (independent of the loads above;
        // store stream overlaps the load stream).
#pragma unroll
        for (int t = 0; t < T_STEPS; t++)
            __stcs(reinterpret_cast<float4*>(out + (size_t)t * N_ELEM + n), zero4);

        float    mem[4] = {0.5f * thre, 0.5f * thre, 0.5f * thre, 0.5f * thre};
        unsigned sb[4]  = {0u, 0u, 0u, 0u};

#pragma unroll
        for (int t = 0; t < T_STEPS; t++) {
            const float v[4] = {xv[t].x, xv[t].y, xv[t].z, xv[t].w};
#pragma unroll
            for (int j = 0; j < 4; j++) {
                mem[j] += v[j];
                if (mem[j] >= thre) {          // heaviside(mem - cur)
                    mem[j] -= thre;            // mem -= s*cur
                    sb[j]  |= (1u << t);
                }
            }
        }

        s_bits[k][threadIdx.x] = sb[0] | (sb[1] << 8) | (sb[2] << 16) | (sb[3] << 24);

        // Compensation pass -> per-element new_thre (cnt via popc).
#pragma unroll
        for (int j = 0; j < 4; j++) {
            const int   cnt = __popc(sb[j]);
            const float cv  = fminf((mem[j] - 0.5f * thre) + (float)cnt * thre,
                                    (float)T_STEPS * thre);
            if (cv > 0.0f && cnt > 0)
                local += cv / (float)cnt;
        }
    }

    const float total = block_sum_256(local, s_ws);

    // ---- Grid barrier (generation-counted, monotonic across replays) ----
    if (threadIdx.x == 0) {
        g_partials[blockIdx.x] = total;
        __threadfence();
        const unsigned old = atomicAdd(&g_arrive, 1u);
        s_gen  = old / GRID1;
        s_last = ((old % GRID1) == GRID1 - 1);
    }
    __syncthreads();

    if (s_last) {
        // Per-channel ub (channel = bid % 128, 8 partials each, fixed order),
        // masked diff, deterministic reduction -> scalar scale.
        float contrib = 0.0f;
        if (threadIdx.x < CHANNELS) {
            float s = 0.0f;
#pragma unroll
            for (int j = 0; j < GRID1 / CHANNELS; j++)
                s += g_partials[threadIdx.x + j * CHANNELS];
            const float ub = s / (float)(BATCH * HW);
            contrib = (thre > ub) ? (ub - thre) : 0.0f;
        }
        const float tot = block_sum_256(contrib, s_ws);
        if (threadIdx.x == 0) {
            g_scale = thre + 0.2f * tot / (float)CHANNELS;    // LR*2 = 0.2
            __threadfence();
            atomicAdd(&g_release, 1u);
        }
    }

    if (threadIdx.x == 0) {
        const unsigned target = s_gen + 1u;
        unsigned v;
        do {
            asm volatile("ld.acquire.gpu.u32 %0, [%1];" : "=r"(v) : "l"(&g_release));
        } while (v < target);
        s_scale = g_scale;
    }
    __syncthreads();

    // ---- Phase C: sparse spike rewrite (only groups containing spikes) ----
    const float scale = s_scale;
#pragma unroll 1
    for (int k = 0; k < SLABS_PER_BLOCK; k++) {
        const uint32_t bits = s_bits[k][threadIdx.x];
        if (bits == 0u) continue;                       // ~50% of groups skip

        const int slab = blockIdx.x + k * GRID1;
        const int n    = slab * HW + threadIdx.x * 4;

        // Timesteps with at least one spike among this thread's 4 elements.
        unsigned m = (bits | (bits >> 8) | (bits >> 16) | (bits >> 24)) & 0xFFu;
        while (m) {
            const int t = __ffs(m) - 1;
            m &= m - 1u;
            float4 o;
            o.x = ((bits >> (t))      & 1u) ? scale : 0.0f;
            o.y = ((bits >> (t + 8))  & 1u) ? scale : 0.0f;
            o.z = ((bits >> (t + 16)) & 1u) ? scale : 0.0f;
            o.w = ((bits >> (t + 24)) & 1u) ? scale : 0.0f;
            __stcs(reinterpret_cast<float4*>(out + (size_t)t * N_ELEM + n), o);
        }
    }
}

// ---------------------------------------------------------------------------
extern "C" void kernel_launch(void* const* d_in, const int* in_sizes, int n_in,
                              void* d_out, int out_size) {
    const float* x      = (const float*)d_in[0];   // [T*B, C, H, W] fp32
    const float* thresh = (const float*)d_in[1];   // [1] fp32
    float*       out    = (float*)d_out;

    if_fused<<<GRID1, 256>>>(x, thresh, out);
}

// round 7
// speedup vs baseline: 1.1238x; 1.1238x over previous
#include <cuda_runtime.h>
#include <cstdint>

// Problem constants (fixed by the reference: T=8, x shape [T*32, 128, 32, 32])
#define T_STEPS   8
#define BATCH     32
#define CHANNELS  128
#define HW        1024                      // 32*32
#define N_ELEM    (BATCH*CHANNELS*HW)       // 4,194,304 spatial positions
#define GRID1     1024                      // single wave; all blocks co-resident
#define SLABS_PER_BLOCK 4                   // slabs b, b+1024, b+2048, b+3072 share channel b%128

// Scratch (static device globals — no runtime allocation permitted).
// Barrier counters are MONOTONIC across graph replays (each replay consumes
// exactly GRID1 arrivals / 1 release) -> no reset, fully deterministic.
__device__ float    g_partials[GRID1];
__device__ float    g_scale;
__device__ unsigned g_arrive  = 0;
__device__ unsigned g_release = 0;

// L2 policy-based eviction hints (128-bit accesses allowed with cache_hint).
__device__ __forceinline__ uint64_t make_policy_evict_first() {
    uint64_t p;
    asm("createpolicy.fractional.L2::evict_first.b64 %0, 1.0;" : "=l"(p));
    return p;
}
__device__ __forceinline__ uint64_t make_policy_evict_last() {
    uint64_t p;
    asm("createpolicy.fractional.L2::evict_last.b64 %0, 1.0;" : "=l"(p));
    return p;
}
// x is single-use streaming data: evict_first so it can't displace the output.
__device__ __forceinline__ float4 ld_stream(const float* p, uint64_t pol) {
    float4 v;
    asm volatile("ld.global.nc.L2::cache_hint.v4.f32 {%0,%1,%2,%3}, [%4], %5;"
                 : "=f"(v.x), "=f"(v.y), "=f"(v.z), "=f"(v.w)
                 : "l"(p), "l"(pol));
    return v;
}
// out is rewritten every replay and read once at the very end: evict_last so
// dirty lines stay in L2 and are overwritten in place instead of going to DRAM.
__device__ __forceinline__ void st_resident(float* p, float4 v, uint64_t pol) {
    asm volatile("st.global.L2::cache_hint.v4.f32 [%0], {%1,%2,%3,%4}, %5;"
                 :: "l"(p), "f"(v.x), "f"(v.y), "f"(v.z), "f"(v.w), "l"(pol)
                 : "memory");
}

// Block-wide deterministic sum (256 threads): shuffle tree + one smem hop.
__device__ __forceinline__ float block_sum_256(float v, float* ws) {
#pragma unroll
    for (int off = 16; off > 0; off >>= 1)
        v += __shfl_down_sync(0xFFFFFFFFu, v, off);
    const int wid = threadIdx.x >> 5;
    if ((threadIdx.x & 31) == 0) ws[wid] = v;
    __syncthreads();
    if (wid == 0) {
        v = (threadIdx.x < 8) ? ws[threadIdx.x] : 0.0f;
#pragma unroll
        for (int off = 4; off > 0; off >>= 1)
            v += __shfl_down_sync(0xFFFFFFFFu, v, off);
    }
    __syncthreads();
    return v;                 // valid in thread 0
}

// ---------------------------------------------------------------------------
// Fused persistent kernel: IF recurrence -> grid barrier -> scaled expansion.
// 1024 blocks, all resident (148 SMs x 7 blocks >= 1024) -> spin is safe.
// ---------------------------------------------------------------------------
__global__ __launch_bounds__(256, 7) void if_fused(const float* __restrict__ x,
                                                   const float* __restrict__ thresh,
                                                   float* __restrict__ out) {
    __shared__ uint32_t s_bits[SLABS_PER_BLOCK][256];   // packed spike bytes, 4 KiB
    __shared__ float    s_ws[8];
    __shared__ float    s_scale;
    __shared__ unsigned s_gen;
    __shared__ int      s_last;

    const float    thre      = __ldg(thresh);
    const uint64_t pol_first = make_policy_evict_first();
    const uint64_t pol_last  = make_policy_evict_last();
    float local = 0.0f;

    // ---- Phase A: recurrence over 4 same-channel slabs ----
#pragma unroll 1
    for (int k = 0; k < SLABS_PER_BLOCK; k++) {
        const int slab = blockIdx.x + k * GRID1;
        const int n    = slab * HW + threadIdx.x * 4;

        float4 xv[T_STEPS];
#pragma unroll
        for (int t = 0; t < T_STEPS; t++)
            xv[t] = ld_stream(x + (size_t)t * N_ELEM + n, pol_first);

        float    mem[4] = {0.5f * thre, 0.5f * thre, 0.5f * thre, 0.5f * thre};
        unsigned sb[4]  = {0u, 0u, 0u, 0u};

#pragma unroll
        for (int t = 0; t < T_STEPS; t++) {
            const float v[4] = {xv[t].x, xv[t].y, xv[t].z, xv[t].w};
#pragma unroll
            for (int j = 0; j < 4; j++) {
                mem[j] += v[j];
                if (mem[j] >= thre) {          // heaviside(mem - cur)
                    mem[j] -= thre;            // mem -= s*cur
                    sb[j]  |= (1u << t);
                }
            }
        }

        s_bits[k][threadIdx.x] = sb[0] | (sb[1] << 8) | (sb[2] << 16) | (sb[3] << 24);

        // Compensation pass -> per-element new_thre (cnt via popc).
#pragma unroll
        for (int j = 0; j < 4; j++) {
            const int   cnt = __popc(sb[j]);
            const float cv  = fminf((mem[j] - 0.5f * thre) + (float)cnt * thre,
                                    (float)T_STEPS * thre);
            if (cv > 0.0f && cnt > 0)
                local += cv / (float)cnt;
        }
    }

    const float total = block_sum_256(local, s_ws);

    // ---- Grid barrier (generation-counted, monotonic across replays) ----
    if (threadIdx.x == 0) {
        g_partials[blockIdx.x] = total;
        __threadfence();
        const unsigned old = atomicAdd(&g_arrive, 1u);
        s_gen  = old / GRID1;
        s_last = ((old % GRID1) == GRID1 - 1);
    }
    __syncthreads();

    if (s_last) {
        // Per-channel ub (channel = bid % 128, 8 partials each, fixed order),
        // masked diff, deterministic reduction -> scalar scale.
        float contrib = 0.0f;
        if (threadIdx.x < CHANNELS) {
            float s = 0.0f;
#pragma unroll
            for (int j = 0; j < GRID1 / CHANNELS; j++)
                s += g_partials[threadIdx.x + j * CHANNELS];
            const float ub = s / (float)(BATCH * HW);
            contrib = (thre > ub) ? (ub - thre) : 0.0f;
        }
        const float tot = block_sum_256(contrib, s_ws);
        if (threadIdx.x == 0) {
            g_scale = thre + 0.2f * tot / (float)CHANNELS;    // LR*2 = 0.2
            __threadfence();
            atomicAdd(&g_release, 1u);
        }
    }

    if (threadIdx.x == 0) {
        const unsigned target = s_gen + 1u;
        unsigned v;
        do {
            asm volatile("ld.acquire.gpu.u32 %0, [%1];" : "=r"(v) : "l"(&g_release));
        } while (v < target);
        s_scale = g_scale;
    }
    __syncthreads();

    // ---- Phase B: expand spike bits * scalar to output (L2-resident) ----
    const float scale = s_scale;
#pragma unroll 1
    for (int k = 0; k < SLABS_PER_BLOCK; k++) {
        const int      slab = blockIdx.x + k * GRID1;
        const int      n    = slab * HW + threadIdx.x * 4;
        const uint32_t bits = s_bits[k][threadIdx.x];

#pragma unroll
        for (int t = 0; t < T_STEPS; t++) {
            float4 o;
            o.x = ((bits >> (t))      & 1u) ? scale : 0.0f;
            o.y = ((bits >> (t + 8))  & 1u) ? scale : 0.0f;
            o.z = ((bits >> (t + 16)) & 1u) ? scale : 0.0f;
            o.w = ((bits >> (t + 24)) & 1u) ? scale : 0.0f;
            st_resident(out + (size_t)t * N_ELEM + n, o, pol_last);
        }
    }
}

// ---------------------------------------------------------------------------
extern "C" void kernel_launch(void* const* d_in, const int* in_sizes, int n_in,
                              void* d_out, int out_size) {
    const float* x      = (const float*)d_in[0];   // [T*B, C, H, W] fp32
    const float* thresh = (const float*)d_in[1];   // [1] fp32
    float*       out    = (float*)d_out;

    if_fused<<<GRID1, 256>>>(x, thresh, out);
}